// round 14
// baseline (speedup 1.0000x reference)
#include <cuda_runtime.h>
#include <cuda_fp16.h>
#include <cstdint>

namespace {
constexpr int NTOK = 16384;
constexpr int DDIM = 2048;
constexpr int RDIM = 256;
}

// Scratch (__device__ globals; no allocation allowed)
__device__ __align__(16) __half g_win[(size_t)DDIM * RDIM];   // W_in fp16 [K=D, M=R]
__device__ __align__(16) __half g_wout[(size_t)RDIM * DDIM];  // W_out fp16 [K=R, M=D]
__device__ __align__(16) __half g_h[(size_t)NTOK * RDIM];     // hidden fp16 [N, R]

__device__ __forceinline__ uint32_t smem_u32(const void* p) {
    return (uint32_t)__cvta_generic_to_shared(p);
}
__device__ __forceinline__ void cp_async16(uint32_t dst, const void* src) {
    asm volatile("cp.async.cg.shared.global [%0], [%1], 16;\n" :: "r"(dst), "l"(src));
}
__device__ __forceinline__ void cp_commit() { asm volatile("cp.async.commit_group;\n" ::: "memory"); }
template <int N>
__device__ __forceinline__ void cp_wait() {
    asm volatile("cp.async.wait_group %0;\n" :: "n"(N) : "memory");
}
__device__ __forceinline__ void ldsm_x4(uint32_t addr, uint32_t& r0, uint32_t& r1,
                                        uint32_t& r2, uint32_t& r3) {
    asm volatile("ldmatrix.sync.aligned.m8n8.x4.shared.b16 {%0,%1,%2,%3}, [%4];\n"
                 : "=r"(r0), "=r"(r1), "=r"(r2), "=r"(r3) : "r"(addr));
}
__device__ __forceinline__ void ldsm_x4_t(uint32_t addr, uint32_t& r0, uint32_t& r1,
                                          uint32_t& r2, uint32_t& r3) {
    asm volatile("ldmatrix.sync.aligned.m8n8.x4.trans.shared.b16 {%0,%1,%2,%3}, [%4];\n"
                 : "=r"(r0), "=r"(r1), "=r"(r2), "=r"(r3) : "r"(addr));
}
__device__ __forceinline__ void mma16816(float* c, const uint32_t* a, uint32_t b0, uint32_t b1) {
    asm volatile(
        "mma.sync.aligned.m16n8k16.row.col.f32.f16.f16.f32 "
        "{%0,%1,%2,%3}, {%4,%5,%6,%7}, {%8,%9}, {%0,%1,%2,%3};\n"
        : "+f"(c[0]), "+f"(c[1]), "+f"(c[2]), "+f"(c[3])
        : "r"(a[0]), "r"(a[1]), "r"(a[2]), "r"(a[3]), "r"(b0), "r"(b1));
}

// ---------------------------------------------------------------------------
// Combined weight prep: 2:4 soft-threshold along last dim, * scale, cast fp16.
// ---------------------------------------------------------------------------
__global__ void prep_both_kernel(const float* __restrict__ w_in,
                                 const float* __restrict__ s_in,
                                 const float* __restrict__ w_out,
                                 const float* __restrict__ s_out) {
    constexpr int ngroups = (DDIM * RDIM) / 4;   // 131072
    int g = blockIdx.x * blockDim.x + threadIdx.x;
    const float* w;
    const float* sc;
    __half* out;
    int gi;
    if (g < ngroups) { w = w_in; sc = s_in; out = g_win; gi = g; }
    else             { w = w_out; sc = s_out; out = g_wout; gi = g - ngroups; }
    float4 v = reinterpret_cast<const float4*>(w)[gi];
    float s = sc[0];
    float a0 = fabsf(v.x), a1 = fabsf(v.y), a2 = fabsf(v.z), a3 = fabsf(v.w);
    float lo1 = fminf(a0, a1), hi1 = fmaxf(a0, a1);
    float lo2 = fminf(a2, a3), hi2 = fmaxf(a2, a3);
    float t = fminf(fmaxf(lo1, lo2), fminf(hi1, hi2));  // 2nd smallest of 4
    float r0 = copysignf(fmaxf(a0 - t, 0.0f), v.x) * s;
    float r1 = copysignf(fmaxf(a1 - t, 0.0f), v.y) * s;
    float r2 = copysignf(fmaxf(a2 - t, 0.0f), v.z) * s;
    float r3 = copysignf(fmaxf(a3 - t, 0.0f), v.w) * s;
    __half2 h01 = __floats2half2_rn(r0, r1);
    __half2 h23 = __floats2half2_rn(r2, r3);
    uint2 pk;
    pk.x = *reinterpret_cast<uint32_t*>(&h01);
    pk.y = *reinterpret_cast<uint32_t*>(&h23);
    reinterpret_cast<uint2*>(out)[gi] = pk;
}

// ---------------------------------------------------------------------------
// GEMM 0 (R12 config, best measured): h[N,256] = fp16(x @ W_in + b_in).
// CTA 64x256xBK32, 128 threads (4 warps of 64x64 tiles), S=4 single-sync
// multistage, 2 CTAs/SM, 256 CTAs. x converted fp32->fp16 on the fly.
// ---------------------------------------------------------------------------
__global__ __launch_bounds__(128, 2)
void gemm0_kernel(const float* __restrict__ x, const float* __restrict__ bias) {
    constexpr int K  = DDIM;
    constexpr int M  = RDIM;
    constexpr int BM = 64, BN = 256, BK = 32;
    constexpr int S  = 4;
    constexpr int KT = K / BK;         // 64
    constexpr int SA = BK + 8;         // 40
    constexpr int SB = BN + 8;         // 264
    constexpr int A_STAGE = BM * SA;
    constexpr int B_STAGE = BK * SB;

    extern __shared__ char dynsm[];
    __half* As   = reinterpret_cast<__half*>(dynsm);
    __half* Bs   = As + S * A_STAGE;
    float* biasS = reinterpret_cast<float*>(Bs + S * B_STAGE);

    const int tid  = threadIdx.x;
    const int lane = tid & 31;
    const int wid  = tid >> 5;
    const int wn   = wid;
    const int bm   = blockIdx.y * BM;

    biasS[tid] = bias[tid];
    biasS[tid + 128] = bias[tid + 128];

    const int arow = lane & 15;
    const int asel = (lane >> 4) * 8;
    const int brow = lane & 15;
    const int bsel = wn * 64 + (lane >> 4) * 8;

    float acc[4][8][4];
#pragma unroll
    for (int i = 0; i < 4; ++i)
#pragma unroll
        for (int j = 0; j < 8; ++j)
#pragma unroll
            for (int k = 0; k < 4; ++k) acc[i][j][k] = 0.0f;

    auto loadB = [&](int kt, int s) {
        const __half* Bg = g_win + (size_t)(kt * BK) * M;
#pragma unroll
        for (int p = 0; p < 8; ++p) {
            int c = tid + p * 128;
            int row = c >> 5, col = (c & 31) * 8;
            cp_async16(smem_u32(&Bs[s * B_STAGE + row * SB + col]),
                       Bg + (size_t)row * M + col);
        }
    };

    float4 a32[4];
    auto ldgA = [&](int kt) {
        const float* Ag = x + (size_t)(bm + (tid >> 1)) * K + kt * BK + (tid & 1) * 16;
#pragma unroll
        for (int p = 0; p < 4; ++p)
            a32[p] = reinterpret_cast<const float4*>(Ag)[p];
    };
    auto stsA = [&](int s) {
        __half h[16];
#pragma unroll
        for (int p = 0; p < 4; ++p) {
            h[p * 4 + 0] = __float2half_rn(a32[p].x);
            h[p * 4 + 1] = __float2half_rn(a32[p].y);
            h[p * 4 + 2] = __float2half_rn(a32[p].z);
            h[p * 4 + 3] = __float2half_rn(a32[p].w);
        }
        int row = tid >> 1, col = (tid & 1) * 16;
        *reinterpret_cast<uint4*>(&As[s * A_STAGE + row * SA + col]) =
            *reinterpret_cast<uint4*>(&h[0]);
        *reinterpret_cast<uint4*>(&As[s * A_STAGE + row * SA + col + 8]) =
            *reinterpret_cast<uint4*>(&h[8]);
    };

#pragma unroll
    for (int s = 0; s < S - 1; ++s) {
        ldgA(s);
        stsA(s);
        loadB(s, s);
        cp_commit();
    }
    ldgA(S - 1);

    for (int kt = 0; kt < KT; ++kt) {
        cp_wait<S - 2>();
        __syncthreads();

        const int ws = (kt + S - 1) % S;
        if (kt + S - 1 < KT) { stsA(ws); loadB(kt + S - 1, ws); }
        cp_commit();
        if (kt + S < KT) ldgA(kt + S);

        const int s = kt % S;
        const uint32_t abase = smem_u32(&As[s * A_STAGE]);
        const uint32_t bbase = smem_u32(&Bs[s * B_STAGE]);

        uint32_t afr[2][4][4];
        uint32_t bfr[2][4];
#pragma unroll
        for (int mi = 0; mi < 4; ++mi)
            ldsm_x4(abase + ((arow + mi * 16) * SA + asel) * 2,
                    afr[0][mi][0], afr[0][mi][1], afr[0][mi][2], afr[0][mi][3]);
        ldsm_x4_t(bbase + (brow * SB + bsel) * 2,
                  bfr[0][0], bfr[0][1], bfr[0][2], bfr[0][3]);

#pragma unroll
        for (int ks = 0; ks < 2; ++ks) {
            const int k0 = ks * 16;
            if (ks == 0) {
#pragma unroll
                for (int mi = 0; mi < 4; ++mi)
                    ldsm_x4(abase + ((arow + mi * 16) * SA + 16 + asel) * 2,
                            afr[1][mi][0], afr[1][mi][1], afr[1][mi][2], afr[1][mi][3]);
            }
#pragma unroll
            for (int np = 0; np < 4; ++np) {
                if (np < 3) {
                    ldsm_x4_t(bbase + ((k0 + brow) * SB + bsel + (np + 1) * 16) * 2,
                              bfr[(np + 1) & 1][0], bfr[(np + 1) & 1][1],
                              bfr[(np + 1) & 1][2], bfr[(np + 1) & 1][3]);
                } else if (ks == 0) {
                    ldsm_x4_t(bbase + ((16 + brow) * SB + bsel) * 2,
                              bfr[0][0], bfr[0][1], bfr[0][2], bfr[0][3]);
                }
                const uint32_t* bf = bfr[np & 1];
#pragma unroll
                for (int mi = 0; mi < 4; ++mi) {
                    mma16816(acc[mi][np * 2],     afr[ks][mi], bf[0], bf[1]);
                    mma16816(acc[mi][np * 2 + 1], afr[ks][mi], bf[2], bf[3]);
                }
            }
        }
    }

    // epilogue -> g_h fp16
    const int col0 = wn * 64;
#pragma unroll
    for (int mi = 0; mi < 4; ++mi) {
#pragma unroll
        for (int ni = 0; ni < 8; ++ni) {
            const int r = bm + mi * 16 + (lane >> 2);
            const int c = col0 + ni * 8 + (lane & 3) * 2;
            const float bb0 = biasS[c];
            const float bb1 = biasS[c + 1];
            __half2* H = reinterpret_cast<__half2*>(g_h);
            H[((size_t)r * M + c) >> 1] =
                __floats2half2_rn(acc[mi][ni][0] + bb0, acc[mi][ni][1] + bb1);
            H[((size_t)(r + 8) * M + c) >> 1] =
                __floats2half2_rn(acc[mi][ni][2] + bb0, acc[mi][ni][3] + bb1);
        }
    }
}

// ---------------------------------------------------------------------------
// GEMM 1 v2: y[N,2048] = h[N,256] @ W_out + b_out (fp32 out).
// Each CTA: 128 rows x 512 cols (4 chunks of 128). A = h[128 x 256] loaded
// ONCE into smem; B streamed double-buffered (S=2, single-sync) over 32
// global k-iterations; chunk epilogue every 8. 512 CTAs, 2 CTAs/SM.
// Amortizes prologue/epilogue 4x and cuts waves 4.6 -> 1.7.
// ---------------------------------------------------------------------------
__global__ __launch_bounds__(128, 2)
void gemm1_kernel(const float* __restrict__ bias, float* __restrict__ y) {
    constexpr int K  = RDIM;         // 256
    constexpr int M  = DDIM;         // 2048
    constexpr int BM = 128, BN = 128, BK = 32;
    constexpr int NCHUNK = 4;
    constexpr int KT = K / BK;       // 8
    constexpr int NJ = NCHUNK * KT;  // 32 global iterations
    constexpr int SA = K + 8;        // 264 halves (A resident, full K)
    constexpr int SB = BN + 8;       // 136
    constexpr int B_STAGE = BK * SB;

    extern __shared__ char dynsm[];
    __half* As   = reinterpret_cast<__half*>(dynsm);                 // 128*264 halves
    __half* Bs   = As + BM * SA;                                     // 2 stages
    float* biasS = reinterpret_cast<float*>(Bs + 2 * B_STAGE);       // 512 floats

    const int tid  = threadIdx.x;
    const int lane = tid & 31;
    const int wid  = tid >> 5;
    const int wm   = wid & 1;          // 0..1
    const int wn   = wid >> 1;         // 0..1
    const int bm   = blockIdx.y * BM;
    const int bn0  = blockIdx.x * (NCHUNK * BN);   // 512-col slab base

#pragma unroll
    for (int p = 0; p < 4; ++p) biasS[tid + p * 128] = bias[bn0 + tid + p * 128];

    const int arow = wm * 64 + (lane & 15);
    const int asel = (lane >> 4) * 8;
    const int brow = lane & 15;
    const int bsel = wn * 64 + (lane >> 4) * 8;

    float acc[4][8][4];
#pragma unroll
    for (int i = 0; i < 4; ++i)
#pragma unroll
        for (int j = 0; j < 8; ++j)
#pragma unroll
            for (int k = 0; k < 4; ++k) acc[i][j][k] = 0.0f;

    // ---- one-time A load: h[bm..bm+128) x K=256 -> resident smem ----
    {
        const __half* Ag = g_h + (size_t)bm * K;
#pragma unroll
        for (int p = 0; p < 32; ++p) {
            int c = tid + p * 128;
            int row = c >> 5, col = (c & 31) * 8;
            cp_async16(smem_u32(&As[row * SA + col]), Ag + (size_t)row * K + col);
        }
    }
    cp_commit();

    auto loadB = [&](int j, int s) {       // global iter j = chunk*8 + kt
        const int ch = j >> 3, kt = j & 7;
        const __half* Bg = g_wout + (size_t)(kt * BK) * M + bn0 + ch * BN;
#pragma unroll
        for (int p = 0; p < 4; ++p) {
            int c = tid + p * 128;
            int row = c >> 4, col = (c & 15) * 8;
            cp_async16(smem_u32(&Bs[s * B_STAGE + row * SB + col]),
                       Bg + (size_t)row * M + col);
        }
    };

    loadB(0, 0);
    cp_commit();

    for (int j = 0; j < NJ; ++j) {
        cp_wait<0>();              // A (first iter) + B stage j resident
        __syncthreads();           // all warps done with stage j-1

        const int ws = (j + 1) & 1;
        if (j + 1 < NJ) loadB(j + 1, ws);
        cp_commit();

        const int kt = j & 7;
        const uint32_t bbase = smem_u32(&Bs[(j & 1) * B_STAGE]);
        const uint32_t abase = smem_u32(As);

#pragma unroll
        for (int ks = 0; ks < 2; ++ks) {
            const int k0 = kt * BK + ks * 16;   // global K offset into resident A
            uint32_t afr[4][4];
#pragma unroll
            for (int mi = 0; mi < 4; ++mi)
                ldsm_x4(abase + ((arow + mi * 16) * SA + k0 + asel) * 2,
                        afr[mi][0], afr[mi][1], afr[mi][2], afr[mi][3]);
#pragma unroll
            for (int np = 0; np < 4; ++np) {
                uint32_t b0, b1, b2, b3;
                ldsm_x4_t(bbase + ((ks * 16 + brow) * SB + bsel + np * 16) * 2,
                          b0, b1, b2, b3);
#pragma unroll
                for (int mi = 0; mi < 4; ++mi) {
                    mma16816(acc[mi][np * 2],     afr[mi], b0, b1);
                    mma16816(acc[mi][np * 2 + 1], afr[mi], b2, b3);
                }
            }
        }

        if (kt == 7) {
            // ---- chunk epilogue -> y fp32, then reset acc ----
            const int ch = j >> 3;
            const int row0 = bm + wm * 64;
            const int col0 = wn * 64;
#pragma unroll
            for (int mi = 0; mi < 4; ++mi) {
#pragma unroll
                for (int ni = 0; ni < 8; ++ni) {
                    const int r  = row0 + mi * 16 + (lane >> 2);
                    const int lc = col0 + ni * 8 + (lane & 3) * 2;
                    const int bc = ch * BN + lc;            // bias index in slab
                    const int gc = bn0 + bc;                // global col
                    const float bb0 = biasS[bc];
                    const float bb1 = biasS[bc + 1];
                    *reinterpret_cast<float2*>(&y[(size_t)r * M + gc]) =
                        make_float2(acc[mi][ni][0] + bb0, acc[mi][ni][1] + bb1);
                    *reinterpret_cast<float2*>(&y[(size_t)(r + 8) * M + gc]) =
                        make_float2(acc[mi][ni][2] + bb0, acc[mi][ni][3] + bb1);
#pragma unroll
                    for (int k = 0; k < 4; ++k) acc[mi][ni][k] = 0.0f;
                }
            }
        }
    }
}

// ---------------------------------------------------------------------------
// kernel_launch. inputs: x, weight_in, weight_out, bias_in, bias_out,
//                        sparse_scale_in, sparse_scale_out
// ---------------------------------------------------------------------------
extern "C" void kernel_launch(void* const* d_in, const int* in_sizes, int n_in,
                              void* d_out, int out_size) {
    const float* x     = (const float*)d_in[0];
    const float* w_in  = (const float*)d_in[1];
    const float* w_out = (const float*)d_in[2];
    const float* b_in  = (const float*)d_in[3];
    const float* b_out = (const float*)d_in[4];
    const float* s_in  = (const float*)d_in[5];
    const float* s_out = (const float*)d_in[6];
    float* y = (float*)d_out;

    constexpr int ngroups = (DDIM * RDIM) / 4;                 // 131072
    prep_both_kernel<<<(2 * ngroups) / 256, 256>>>(w_in, s_in, w_out, s_out);

    constexpr int SMEM0 = 4 * (64 * 40 + 32 * 264) * 2 + 256 * 4;        // 89600
    constexpr int SMEM1 = (128 * 264 + 2 * 32 * 136) * 2 + 512 * 4;      // 86528
    cudaFuncSetAttribute(gemm0_kernel, cudaFuncAttributeMaxDynamicSharedMemorySize, SMEM0);
    cudaFuncSetAttribute(gemm1_kernel, cudaFuncAttributeMaxDynamicSharedMemorySize, SMEM1);

    dim3 g0(1, NTOK / 64);             // 256 CTAs
    gemm0_kernel<<<g0, 128, SMEM0>>>(x, b_in);

    dim3 g1(DDIM / 512, NTOK / 128);   // (4, 128) = 512 CTAs
    gemm1_kernel<<<g1, 128, SMEM1>>>(b_out, y);
}

// round 15
// speedup vs baseline: 1.0564x; 1.0564x over previous
#include <cuda_runtime.h>
#include <cuda_fp16.h>
#include <cstdint>

namespace {
constexpr int NTOK = 16384;
constexpr int DDIM = 2048;
constexpr int RDIM = 256;
}

// Scratch (__device__ globals; no allocation allowed)
__device__ __align__(16) __half g_win[(size_t)DDIM * RDIM];   // W_in fp16 [K=D, M=R]
__device__ __align__(16) __half g_wout[(size_t)RDIM * DDIM];  // W_out fp16 [K=R, M=D]
__device__ __align__(16) __half g_h[(size_t)NTOK * RDIM];     // hidden fp16 [N, R]

__device__ __forceinline__ uint32_t smem_u32(const void* p) {
    return (uint32_t)__cvta_generic_to_shared(p);
}
__device__ __forceinline__ void cp_async16(uint32_t dst, const void* src) {
    asm volatile("cp.async.cg.shared.global [%0], [%1], 16;\n" :: "r"(dst), "l"(src));
}
__device__ __forceinline__ void cp_commit() { asm volatile("cp.async.commit_group;\n" ::: "memory"); }
template <int N>
__device__ __forceinline__ void cp_wait() {
    asm volatile("cp.async.wait_group %0;\n" :: "n"(N) : "memory");
}
__device__ __forceinline__ void griddep_launch() {
    asm volatile("griddepcontrol.launch_dependents;" ::: "memory");
}
__device__ __forceinline__ void griddep_wait() {
    asm volatile("griddepcontrol.wait;" ::: "memory");
}
__device__ __forceinline__ void ldsm_x4(uint32_t addr, uint32_t& r0, uint32_t& r1,
                                        uint32_t& r2, uint32_t& r3) {
    asm volatile("ldmatrix.sync.aligned.m8n8.x4.shared.b16 {%0,%1,%2,%3}, [%4];\n"
                 : "=r"(r0), "=r"(r1), "=r"(r2), "=r"(r3) : "r"(addr));
}
__device__ __forceinline__ void ldsm_x4_t(uint32_t addr, uint32_t& r0, uint32_t& r1,
                                          uint32_t& r2, uint32_t& r3) {
    asm volatile("ldmatrix.sync.aligned.m8n8.x4.trans.shared.b16 {%0,%1,%2,%3}, [%4];\n"
                 : "=r"(r0), "=r"(r1), "=r"(r2), "=r"(r3) : "r"(addr));
}
__device__ __forceinline__ void mma16816(float* c, const uint32_t* a, uint32_t b0, uint32_t b1) {
    asm volatile(
        "mma.sync.aligned.m16n8k16.row.col.f32.f16.f16.f32 "
        "{%0,%1,%2,%3}, {%4,%5,%6,%7}, {%8,%9}, {%0,%1,%2,%3};\n"
        : "+f"(c[0]), "+f"(c[1]), "+f"(c[2]), "+f"(c[3])
        : "r"(a[0]), "r"(a[1]), "r"(a[2]), "r"(a[3]), "r"(b0), "r"(b1));
}

// ---------------------------------------------------------------------------
// Combined weight prep: 2:4 soft-threshold along last dim, * scale, cast fp16.
// ---------------------------------------------------------------------------
__global__ void prep_both_kernel(const float* __restrict__ w_in,
                                 const float* __restrict__ s_in,
                                 const float* __restrict__ w_out,
                                 const float* __restrict__ s_out) {
    constexpr int ngroups = (DDIM * RDIM) / 4;   // 131072
    int g = blockIdx.x * blockDim.x + threadIdx.x;
    const float* w;
    const float* sc;
    __half* out;
    int gi;
    if (g < ngroups) { w = w_in; sc = s_in; out = g_win; gi = g; }
    else             { w = w_out; sc = s_out; out = g_wout; gi = g - ngroups; }
    float4 v = reinterpret_cast<const float4*>(w)[gi];
    float s = sc[0];
    float a0 = fabsf(v.x), a1 = fabsf(v.y), a2 = fabsf(v.z), a3 = fabsf(v.w);
    float lo1 = fminf(a0, a1), hi1 = fmaxf(a0, a1);
    float lo2 = fminf(a2, a3), hi2 = fmaxf(a2, a3);
    float t = fminf(fmaxf(lo1, lo2), fminf(hi1, hi2));  // 2nd smallest of 4
    float r0 = copysignf(fmaxf(a0 - t, 0.0f), v.x) * s;
    float r1 = copysignf(fmaxf(a1 - t, 0.0f), v.y) * s;
    float r2 = copysignf(fmaxf(a2 - t, 0.0f), v.z) * s;
    float r3 = copysignf(fmaxf(a3 - t, 0.0f), v.w) * s;
    __half2 h01 = __floats2half2_rn(r0, r1);
    __half2 h23 = __floats2half2_rn(r2, r3);
    uint2 pk;
    pk.x = *reinterpret_cast<uint32_t*>(&h01);
    pk.y = *reinterpret_cast<uint32_t*>(&h23);
    reinterpret_cast<uint2*>(out)[gi] = pk;
}

// ---------------------------------------------------------------------------
// GEMM 0 (R12 config, best measured): h[N,256] = fp16(x @ W_in + b_in).
// CTA 64x256xBK32, 128 threads (4 warps of 64x64 tiles), S=4 single-sync
// multistage, 2 CTAs/SM, 256 CTAs. x converted fp32->fp16 on the fly.
// PDL: launch_dependents after the k-loop so gemm1 overlaps the epilogue.
// ---------------------------------------------------------------------------
__global__ __launch_bounds__(128, 2)
void gemm0_kernel(const float* __restrict__ x, const float* __restrict__ bias) {
    constexpr int K  = DDIM;
    constexpr int M  = RDIM;
    constexpr int BM = 64, BN = 256, BK = 32;
    constexpr int S  = 4;
    constexpr int KT = K / BK;         // 64
    constexpr int SA = BK + 8;         // 40
    constexpr int SB = BN + 8;         // 264
    constexpr int A_STAGE = BM * SA;
    constexpr int B_STAGE = BK * SB;

    extern __shared__ char dynsm[];
    __half* As   = reinterpret_cast<__half*>(dynsm);
    __half* Bs   = As + S * A_STAGE;
    float* biasS = reinterpret_cast<float*>(Bs + S * B_STAGE);

    const int tid  = threadIdx.x;
    const int lane = tid & 31;
    const int wid  = tid >> 5;
    const int wn   = wid;
    const int bm   = blockIdx.y * BM;

    biasS[tid] = bias[tid];
    biasS[tid + 128] = bias[tid + 128];

    const int arow = lane & 15;
    const int asel = (lane >> 4) * 8;
    const int brow = lane & 15;
    const int bsel = wn * 64 + (lane >> 4) * 8;

    float acc[4][8][4];
#pragma unroll
    for (int i = 0; i < 4; ++i)
#pragma unroll
        for (int j = 0; j < 8; ++j)
#pragma unroll
            for (int k = 0; k < 4; ++k) acc[i][j][k] = 0.0f;

    auto loadB = [&](int kt, int s) {
        const __half* Bg = g_win + (size_t)(kt * BK) * M;
#pragma unroll
        for (int p = 0; p < 8; ++p) {
            int c = tid + p * 128;
            int row = c >> 5, col = (c & 31) * 8;
            cp_async16(smem_u32(&Bs[s * B_STAGE + row * SB + col]),
                       Bg + (size_t)row * M + col);
        }
    };

    float4 a32[4];
    auto ldgA = [&](int kt) {
        const float* Ag = x + (size_t)(bm + (tid >> 1)) * K + kt * BK + (tid & 1) * 16;
#pragma unroll
        for (int p = 0; p < 4; ++p)
            a32[p] = reinterpret_cast<const float4*>(Ag)[p];
    };
    auto stsA = [&](int s) {
        __half h[16];
#pragma unroll
        for (int p = 0; p < 4; ++p) {
            h[p * 4 + 0] = __float2half_rn(a32[p].x);
            h[p * 4 + 1] = __float2half_rn(a32[p].y);
            h[p * 4 + 2] = __float2half_rn(a32[p].z);
            h[p * 4 + 3] = __float2half_rn(a32[p].w);
        }
        int row = tid >> 1, col = (tid & 1) * 16;
        *reinterpret_cast<uint4*>(&As[s * A_STAGE + row * SA + col]) =
            *reinterpret_cast<uint4*>(&h[0]);
        *reinterpret_cast<uint4*>(&As[s * A_STAGE + row * SA + col + 8]) =
            *reinterpret_cast<uint4*>(&h[8]);
    };

#pragma unroll
    for (int s = 0; s < S - 1; ++s) {
        ldgA(s);
        stsA(s);
        loadB(s, s);
        cp_commit();
    }
    ldgA(S - 1);

    for (int kt = 0; kt < KT; ++kt) {
        cp_wait<S - 2>();
        __syncthreads();

        const int ws = (kt + S - 1) % S;
        if (kt + S - 1 < KT) { stsA(ws); loadB(kt + S - 1, ws); }
        cp_commit();
        if (kt + S < KT) ldgA(kt + S);

        const int s = kt % S;
        const uint32_t abase = smem_u32(&As[s * A_STAGE]);
        const uint32_t bbase = smem_u32(&Bs[s * B_STAGE]);

        uint32_t afr[2][4][4];
        uint32_t bfr[2][4];
#pragma unroll
        for (int mi = 0; mi < 4; ++mi)
            ldsm_x4(abase + ((arow + mi * 16) * SA + asel) * 2,
                    afr[0][mi][0], afr[0][mi][1], afr[0][mi][2], afr[0][mi][3]);
        ldsm_x4_t(bbase + (brow * SB + bsel) * 2,
                  bfr[0][0], bfr[0][1], bfr[0][2], bfr[0][3]);

#pragma unroll
        for (int ks = 0; ks < 2; ++ks) {
            const int k0 = ks * 16;
            if (ks == 0) {
#pragma unroll
                for (int mi = 0; mi < 4; ++mi)
                    ldsm_x4(abase + ((arow + mi * 16) * SA + 16 + asel) * 2,
                            afr[1][mi][0], afr[1][mi][1], afr[1][mi][2], afr[1][mi][3]);
            }
#pragma unroll
            for (int np = 0; np < 4; ++np) {
                if (np < 3) {
                    ldsm_x4_t(bbase + ((k0 + brow) * SB + bsel + (np + 1) * 16) * 2,
                              bfr[(np + 1) & 1][0], bfr[(np + 1) & 1][1],
                              bfr[(np + 1) & 1][2], bfr[(np + 1) & 1][3]);
                } else if (ks == 0) {
                    ldsm_x4_t(bbase + ((16 + brow) * SB + bsel) * 2,
                              bfr[0][0], bfr[0][1], bfr[0][2], bfr[0][3]);
                }
                const uint32_t* bf = bfr[np & 1];
#pragma unroll
                for (int mi = 0; mi < 4; ++mi) {
                    mma16816(acc[mi][np * 2],     afr[ks][mi], bf[0], bf[1]);
                    mma16816(acc[mi][np * 2 + 1], afr[ks][mi], bf[2], bf[3]);
                }
            }
        }
    }

    // PDL: all compute done; let gemm1 start launching while we store g_h.
    griddep_launch();

    // epilogue -> g_h fp16
    const int col0 = wn * 64;
#pragma unroll
    for (int mi = 0; mi < 4; ++mi) {
#pragma unroll
        for (int ni = 0; ni < 8; ++ni) {
            const int r = bm + mi * 16 + (lane >> 2);
            const int c = col0 + ni * 8 + (lane & 3) * 2;
            const float bb0 = biasS[c];
            const float bb1 = biasS[c + 1];
            __half2* H = reinterpret_cast<__half2*>(g_h);
            H[((size_t)r * M + c) >> 1] =
                __floats2half2_rn(acc[mi][ni][0] + bb0, acc[mi][ni][1] + bb1);
            H[((size_t)(r + 8) * M + c) >> 1] =
                __floats2half2_rn(acc[mi][ni][2] + bb0, acc[mi][ni][3] + bb1);
        }
    }
}

// ---------------------------------------------------------------------------
// GEMM 1 (R12 config): y[N,2048] = h[N,256] @ W_out + b_out (fp32 out).
// 128 threads (4 warps, 2x2 of 64x64 tiles), BM128/BN128/BK32, S=2
// single-sync multistage, 3 CTAs/SM.
// PDL: front-load bias + B stage 0 (g_wout, prep-dependent only), then
// griddepcontrol.wait before touching g_h.
// ---------------------------------------------------------------------------
__global__ __launch_bounds__(128, 3)
void gemm1_kernel(const float* __restrict__ bias, float* __restrict__ y) {
    constexpr int K  = RDIM;
    constexpr int M  = DDIM;
    constexpr int BM = 128, BN = 128, BK = 32;
    constexpr int S  = 2;
    constexpr int KT = K / BK;    // 8
    constexpr int SA = BK + 8;    // 40
    constexpr int SB = BN + 8;    // 136
    constexpr int A_STAGE = BM * SA;
    constexpr int B_STAGE = BK * SB;

    extern __shared__ char dynsm[];
    __half* As   = reinterpret_cast<__half*>(dynsm);
    __half* Bs   = As + S * A_STAGE;
    float* biasS = reinterpret_cast<float*>(Bs + S * B_STAGE);

    const int tid  = threadIdx.x;
    const int lane = tid & 31;
    const int wid  = tid >> 5;
    const int wm   = wid & 1;          // 0..1
    const int wn   = wid >> 1;         // 0..1
    const int bm   = blockIdx.y * BM;
    const int bn   = blockIdx.x * BN;

    const int arow = wm * 64 + (lane & 15);
    const int asel = (lane >> 4) * 8;
    const int brow = lane & 15;
    const int bsel = wn * 64 + (lane >> 4) * 8;

    float acc[4][8][4];
#pragma unroll
    for (int i = 0; i < 4; ++i)
#pragma unroll
        for (int j = 0; j < 8; ++j)
#pragma unroll
            for (int k = 0; k < 4; ++k) acc[i][j][k] = 0.0f;

    auto loadA = [&](int kt, int s) {
        const __half* Ag = g_h + (size_t)bm * K + kt * BK;
#pragma unroll
        for (int p = 0; p < 4; ++p) {
            int c = tid + p * 128;
            int row = c >> 2, col = (c & 3) * 8;
            cp_async16(smem_u32(&As[s * A_STAGE + row * SA + col]),
                       Ag + (size_t)row * K + col);
        }
    };
    auto loadB = [&](int kt, int s) {
        const __half* Bg = g_wout + (size_t)(kt * BK) * M + bn;
#pragma unroll
        for (int p = 0; p < 4; ++p) {
            int c = tid + p * 128;
            int row = c >> 4, col = (c & 15) * 8;
            cp_async16(smem_u32(&Bs[s * B_STAGE + row * SB + col]),
                       Bg + (size_t)row * M + col);
        }
    };

    // pre-wait work: depends only on prep (done before gemm0 started)
    biasS[tid] = bias[bn + tid];
    loadB(0, 0);

    // gemm0's g_h must be fully visible before A loads
    griddep_wait();

    loadA(0, 0);
    cp_commit();

    for (int kt = 0; kt < KT; ++kt) {
        cp_wait<0>();              // tile kt resident
        __syncthreads();           // all warps done with tile kt-1

        const int ws = (kt + 1) & 1;
        if (kt + 1 < KT) { loadA(kt + 1, ws); loadB(kt + 1, ws); }
        cp_commit();

        const int s = kt & 1;
        const uint32_t abase = smem_u32(&As[s * A_STAGE]);
        const uint32_t bbase = smem_u32(&Bs[s * B_STAGE]);

#pragma unroll
        for (int ks = 0; ks < 2; ++ks) {
            const int k0 = ks * 16;
            uint32_t afr[4][4];
#pragma unroll
            for (int mi = 0; mi < 4; ++mi)
                ldsm_x4(abase + ((arow + mi * 16) * SA + k0 + asel) * 2,
                        afr[mi][0], afr[mi][1], afr[mi][2], afr[mi][3]);
#pragma unroll
            for (int np = 0; np < 4; ++np) {
                uint32_t b0, b1, b2, b3;
                ldsm_x4_t(bbase + ((k0 + brow) * SB + bsel + np * 16) * 2,
                          b0, b1, b2, b3);
#pragma unroll
                for (int mi = 0; mi < 4; ++mi) {
                    mma16816(acc[mi][np * 2],     afr[mi], b0, b1);
                    mma16816(acc[mi][np * 2 + 1], afr[mi], b2, b3);
                }
            }
        }
    }

    // epilogue -> y fp32
    const int row0 = bm + wm * 64;
    const int col0 = wn * 64;
#pragma unroll
    for (int mi = 0; mi < 4; ++mi) {
#pragma unroll
        for (int ni = 0; ni < 8; ++ni) {
            const int r  = row0 + mi * 16 + (lane >> 2);
            const int lc = col0 + ni * 8 + (lane & 3) * 2;
            const int gc = bn + lc;
            const float bb0 = biasS[lc];
            const float bb1 = biasS[lc + 1];
            *reinterpret_cast<float2*>(&y[(size_t)r * M + gc]) =
                make_float2(acc[mi][ni][0] + bb0, acc[mi][ni][1] + bb1);
            *reinterpret_cast<float2*>(&y[(size_t)(r + 8) * M + gc]) =
                make_float2(acc[mi][ni][2] + bb0, acc[mi][ni][3] + bb1);
        }
    }
}

// ---------------------------------------------------------------------------
// kernel_launch. inputs: x, weight_in, weight_out, bias_in, bias_out,
//                        sparse_scale_in, sparse_scale_out
// ---------------------------------------------------------------------------
extern "C" void kernel_launch(void* const* d_in, const int* in_sizes, int n_in,
                              void* d_out, int out_size) {
    const float* x     = (const float*)d_in[0];
    const float* w_in  = (const float*)d_in[1];
    const float* w_out = (const float*)d_in[2];
    const float* b_in  = (const float*)d_in[3];
    const float* b_out = (const float*)d_in[4];
    const float* s_in  = (const float*)d_in[5];
    const float* s_out = (const float*)d_in[6];
    float* y = (float*)d_out;

    constexpr int ngroups = (DDIM * RDIM) / 4;                 // 131072
    prep_both_kernel<<<(2 * ngroups) / 256, 256>>>(w_in, s_in, w_out, s_out);

    constexpr int SMEM0 = 4 * (64 * 40 + 32 * 264) * 2 + 256 * 4;   // 89600
    constexpr int SMEM1 = 2 * (128 * 40 + 32 * 136) * 2 + 128 * 4;  // 38400
    static bool attr_done = false;
    if (!attr_done) {
        cudaFuncSetAttribute(gemm0_kernel, cudaFuncAttributeMaxDynamicSharedMemorySize, SMEM0);
        cudaFuncSetAttribute(gemm1_kernel, cudaFuncAttributeMaxDynamicSharedMemorySize, SMEM1);
        attr_done = true;
    }

    dim3 g0(1, NTOK / 64);             // 256 CTAs
    gemm0_kernel<<<g0, 128, SMEM0>>>(x, b_in);

    // gemm1 with programmatic dependent launch: overlaps gemm0's epilogue.
    {
        cudaLaunchConfig_t cfg = {};
        cfg.gridDim  = dim3(DDIM / 128, NTOK / 128);   // (16, 128) = 2048 CTAs
        cfg.blockDim = dim3(128, 1, 1);
        cfg.dynamicSmemBytes = SMEM1;
        cudaLaunchAttribute attrs[1];
        attrs[0].id = cudaLaunchAttributeProgrammaticStreamSerialization;
        attrs[0].val.programmaticStreamSerializationAllowed = 1;
        cfg.attrs = attrs;
        cfg.numAttrs = 1;
        cudaLaunchKernelEx(&cfg, gemm1_kernel, (const float*)b_out, (float*)y);
    }
}